// round 16
// baseline (speedup 1.0000x reference)
#include <cuda_runtime.h>
#include <cuda_bf16.h>
#include <math.h>

typedef unsigned long long u64;
typedef unsigned int u32;

// ---------------- constants ----------------
#define B_  64
#define S_  50
#define T_  50
#define R_  2
#define H_  256
#define NU_ (B_*S_)          // 3200
#define NR_ (B_*R_)          // 128
#define NALL_ (NU_+NR_)      // 3328
#define MU_ (T_*NU_)         // 160000
#define MR_ (T_*NR_)         // 6400
#define MC_ (S_*B_)          // 3200
#define TAB_N (B_*(S_+1)*H_) // 835584

// output offsets (f32 elements)
#define OFF_CTXOUT   0
#define OFF_CTXHID   819200
#define OFF_RESPOUT  835584
#define OFF_RESPHID  2473984
#define OFF_SPKEMB   2506752
#define OFF_MASK     3342336

// ---------------- static device scratch ----------------
__device__ float g_tables[TAB_N];
__device__ float g_GIu[(size_t)MU_*768];
__device__ float g_GIc[(size_t)MC_*768];
__device__ float g_GIr[(size_t)MR_*768];
__device__ float g_hall[NALL_*H_];
__device__ float g_hc[B_*H_];
__device__ float g_hspk[B_*(S_+1)*H_];
__device__ float g_ctxin[MC_*2*H_];
__device__ float g_WTc_i[2*H_*768], g_WTc_h[H_*768];
__device__ float g_WTs_i[H_*768],  g_WTs_h[H_*768];
__device__ __nv_bfloat16 g_WuT[16*24576],  g_WrT[16*24576];    // Whh (recurrence)
__device__ __nv_bfloat16 g_WuiT[16*24576], g_WriT[16*24576];   // Wih (input GEMM)
__device__ int   g_toku[MU_];
__device__ int   g_tokr[MR_];
__device__ int   g_present[B_*(S_+1)];

// ---------------- helpers ----------------
__device__ __forceinline__ u64 pack2(float lo, float hi) {
    u64 r; asm("mov.b64 %0, {%1,%2};" : "=l"(r) : "f"(lo), "f"(hi)); return r;
}
__device__ __forceinline__ void unpack2(u64 a, float& lo, float& hi) {
    asm("mov.b64 {%0,%1}, %2;" : "=f"(lo), "=f"(hi) : "l"(a));
}
__device__ __forceinline__ u64 ffma2(u64 a, u64 b, u64 c) {
    u64 d; asm("fma.rn.f32x2 %0, %1, %2, %3;" : "=l"(d) : "l"(a), "l"(b), "l"(c)); return d;
}
__device__ __forceinline__ void ldx4(u32* r, u32 addr) {
    asm volatile("ldmatrix.sync.aligned.m8n8.x4.shared.b16 {%0,%1,%2,%3}, [%4];"
        : "=r"(r[0]), "=r"(r[1]), "=r"(r[2]), "=r"(r[3]) : "r"(addr));
}
__device__ __forceinline__ void mma_bf16(float* c, const u32* a, u32 b0, u32 b1) {
    asm volatile(
        "mma.sync.aligned.m16n8k16.row.col.f32.bf16.bf16.f32 "
        "{%0,%1,%2,%3}, {%4,%5,%6,%7}, {%8,%9}, {%0,%1,%2,%3};"
        : "+f"(c[0]), "+f"(c[1]), "+f"(c[2]), "+f"(c[3])
        : "r"(a[0]), "r"(a[1]), "r"(a[2]), "r"(a[3]), "r"(b0), "r"(b1));
}
__device__ __forceinline__ void mbar_init(u32 a, u32 c) {
    asm volatile("mbarrier.init.shared.b64 [%0], %1;" :: "r"(a), "r"(c) : "memory");
}
__device__ __forceinline__ void mbar_expect(u32 a, u32 bytes) {
    asm volatile("mbarrier.arrive.expect_tx.shared.b64 _, [%0], %1;" :: "r"(a), "r"(bytes) : "memory");
}
__device__ __forceinline__ void mbar_wait(u32 a, u32 parity) {
    u32 done;
    asm volatile(
        "{\n\t.reg .pred p;\n\t"
        "mbarrier.try_wait.parity.acquire.cta.shared::cta.b64 p, [%1], %2;\n\t"
        "selp.b32 %0, 1, 0, p;\n\t}"
        : "=r"(done) : "r"(a), "r"(parity) : "memory");
    if (!done) {
        asm volatile(
            "{\n\t.reg .pred P1;\n\t"
            "WL_%=:\n\t"
            "mbarrier.try_wait.parity.acquire.cta.shared::cta.b64 P1, [%0], %1, 0x989680;\n\t"
            "@P1 bra.uni WD_%=;\n\t"
            "bra.uni WL_%=;\n\t"
            "WD_%=:\n\t}"
            :: "r"(a), "r"(parity) : "memory");
    }
}
__device__ __forceinline__ void cp_bulk(u32 dst_smem, const void* src, u32 bytes, u32 mbar) {
    asm volatile("cp.async.bulk.shared::cta.global.mbarrier::complete_tx::bytes [%0], [%1], %2, [%3];"
        :: "r"(dst_smem), "l"(src), "r"(bytes), "r"(mbar) : "memory");
}
__device__ __forceinline__ u32 swz32(u32 x) { return x ^ ((x >> 3) & 0x70); }

// ---------------- MT19937 (NumPy-exact state; fp32 output conversion) ----------------
__device__ __forceinline__ unsigned mt_twist_fn(unsigned u, unsigned v) {
    unsigned y = (u & 0x80000000u) | (v & 0x7fffffffu);
    return (y >> 1) ^ ((v & 1u) ? 0x9908b0dfu : 0u);
}
__device__ __forceinline__ unsigned mt_temper(unsigned y) {
    y ^= y >> 11; y ^= (y << 7) & 0x9d2c5680u; y ^= (y << 15) & 0xefc60000u; y ^= y >> 18;
    return y;
}
__device__ void mt_body(float* __restrict__ tables, unsigned* bufA, unsigned* bufB) {
    const int tid = threadIdx.x;
    const int nthr = blockDim.x;
    if (tid == 0) {
        unsigned s = 1u; bufA[0] = s;
        for (int i = 1; i < 624; i++) { s = 1812433253u * (s ^ (s >> 30)) + (unsigned)i; bufA[i] = s; }
    }
    __syncthreads();
    unsigned* cur = bufA; unsigned* nxt = bufB;
    const int NTW = (2*TAB_N + 623) / 624;
    for (int tw = 0; tw < NTW; tw++) {
        if (tid < 227) nxt[tid] = cur[tid + 397] ^ mt_twist_fn(cur[tid], cur[tid + 1]);
        __syncthreads();
        if (tid < 227) { int i = 227 + tid; nxt[i] = nxt[i - 227] ^ mt_twist_fn(cur[i], cur[i + 1]); }
        __syncthreads();
        if (tid < 170) {
            int i = 454 + tid;
            unsigned v = (i == 623) ? nxt[0] : cur[i + 1];
            nxt[i] = nxt[i - 227] ^ mt_twist_fn(cur[i], v);
        }
        __syncthreads();
        for (int o = tid; o < 312; o += nthr) {
            int outIdx = tw * 312 + o;
            if (outIdx < TAB_N) {
                unsigned a  = mt_temper(nxt[2*o])   >> 5;
                unsigned bv = mt_temper(nxt[2*o+1]) >> 6;
                tables[outIdx] = fmaf((float)a, 67108864.0f, (float)bv) * (1.0f/9007199254740992.0f);
            }
        }
        unsigned* t2 = cur; cur = nxt; nxt = t2;
    }
}

// ---------------- fp32 GEMM body (ctx path only) ----------------
__device__ __forceinline__ void gemm_body(
    const float* __restrict__ A,
    const float* __restrict__ BT, const float* __restrict__ bias, float* __restrict__ C,
    int m0, int n0, int K, float* As, float* Bs)
{
    const int tid  = threadIdx.x;
    const int arow = tid >> 2;
    const int akc  = (tid & 3) << 2;
    const int bk   = tid >> 4;
    const int bc   = (tid & 15) << 3;
    const int tr   = tid >> 4;
    const int tc   = tid & 15;

    const float* arp0 = A + (size_t)(m0 + arow) * K;
    const float* arp1 = A + (size_t)(m0 + arow + 64) * K;
    float4 ra0 = *(const float4*)(arp0 + akc);
    float4 ra1 = *(const float4*)(arp1 + akc);
    float4 rb0 = *(const float4*)(BT + (size_t)bk * 768 + n0 + bc);
    float4 rb1 = *(const float4*)(BT + (size_t)bk * 768 + n0 + bc + 4);
    {
        As[(akc+0)*128 + arow] = ra0.x; As[(akc+1)*128 + arow] = ra0.y;
        As[(akc+2)*128 + arow] = ra0.z; As[(akc+3)*128 + arow] = ra0.w;
        As[(akc+0)*128 + arow+64] = ra1.x; As[(akc+1)*128 + arow+64] = ra1.y;
        As[(akc+2)*128 + arow+64] = ra1.z; As[(akc+3)*128 + arow+64] = ra1.w;
        *(float4*)(Bs + bk*128 + bc)     = rb0;
        *(float4*)(Bs + bk*128 + bc + 4) = rb1;
    }
    __syncthreads();

    u64 acc[8][4];
    #pragma unroll
    for (int i = 0; i < 8; i++)
        #pragma unroll
        for (int j = 0; j < 4; j++) acc[i][j] = 0ull;

    int buf = 0;
    for (int k0 = 16; k0 <= K; k0 += 16) {
        const bool more = (k0 < K);
        if (more) {
            ra0 = *(const float4*)(arp0 + k0 + akc);
            ra1 = *(const float4*)(arp1 + k0 + akc);
            rb0 = *(const float4*)(BT + (size_t)(k0 + bk) * 768 + n0 + bc);
            rb1 = *(const float4*)(BT + (size_t)(k0 + bk) * 768 + n0 + bc + 4);
        }
        const float* Asb = As + buf * 2048;
        const float* Bsb = Bs + buf * 2048;
        #pragma unroll
        for (int kk = 0; kk < 16; kk++) {
            float4 av0 = *(const float4*)(Asb + kk*128 + tr*8);
            float4 av1 = *(const float4*)(Asb + kk*128 + tr*8 + 4);
            u64 bb0 = *(const u64*)(Bsb + kk*128 + tc*4);
            u64 bb1 = *(const u64*)(Bsb + kk*128 + tc*4 + 2);
            u64 bb2 = *(const u64*)(Bsb + kk*128 + 64 + tc*4);
            u64 bb3 = *(const u64*)(Bsb + kk*128 + 64 + tc*4 + 2);
            float av[8] = {av0.x, av0.y, av0.z, av0.w, av1.x, av1.y, av1.z, av1.w};
            #pragma unroll
            for (int i = 0; i < 8; i++) {
                u64 aa = pack2(av[i], av[i]);
                acc[i][0] = ffma2(aa, bb0, acc[i][0]);
                acc[i][1] = ffma2(aa, bb1, acc[i][1]);
                acc[i][2] = ffma2(aa, bb2, acc[i][2]);
                acc[i][3] = ffma2(aa, bb3, acc[i][3]);
            }
        }
        if (more) {
            float* Asb1 = As + (buf ^ 1) * 2048;
            float* Bsb1 = Bs + (buf ^ 1) * 2048;
            Asb1[(akc+0)*128 + arow] = ra0.x; Asb1[(akc+1)*128 + arow] = ra0.y;
            Asb1[(akc+2)*128 + arow] = ra0.z; Asb1[(akc+3)*128 + arow] = ra0.w;
            Asb1[(akc+0)*128 + arow+64] = ra1.x; Asb1[(akc+1)*128 + arow+64] = ra1.y;
            Asb1[(akc+2)*128 + arow+64] = ra1.z; Asb1[(akc+3)*128 + arow+64] = ra1.w;
            *(float4*)(Bsb1 + bk*128 + bc)     = rb0;
            *(float4*)(Bsb1 + bk*128 + bc + 4) = rb1;
        }
        __syncthreads();
        buf ^= 1;
    }

    float4 bba = *(const float4*)(bias + n0 + tc*4);
    float4 bbb = *(const float4*)(bias + n0 + 64 + tc*4);
    #pragma unroll
    for (int i = 0; i < 8; i++) {
        int gm = m0 + tr*8 + i;
        float x0,x1,x2,x3,y0,y1,y2,y3;
        unpack2(acc[i][0], x0, x1); unpack2(acc[i][1], x2, x3);
        unpack2(acc[i][2], y0, y1); unpack2(acc[i][3], y2, y3);
        float4 o0 = make_float4(x0+bba.x, x1+bba.y, x2+bba.z, x3+bba.w);
        float4 o1 = make_float4(y0+bbb.x, y1+bbb.y, y2+bbb.z, y3+bbb.w);
        *(float4*)(C + (size_t)gm*768 + n0 + tc*4)      = o0;
        *(float4*)(C + (size_t)gm*768 + n0 + 64 + tc*4) = o1;
    }
}

__global__ __launch_bounds__(256) void gemm_ctx_kernel(
    const float* __restrict__ cin, const float* __restrict__ WTc_i,
    const float* __restrict__ cbih, float* __restrict__ GIc)
{
    __shared__ float As[2*16*128];
    __shared__ float Bs[2*16*128];
    int mb = blockIdx.x % 25, nb = blockIdx.x / 25;
    gemm_body(cin, WTc_i, cbih, GIc, mb*128, nb*128, 512, As, Bs);
}

// ---------------- tensorized input GEMM ----------------
#define HP_ 264
#define WKTILE_B 49152
#define MG_HHI   64
#define MG_HLO   (64 + 16896)
#define MG_WBUF  (64 + 33792)
#define SMEM_MEGA (MG_WBUF + 2*WKTILE_B)   // 132160

__global__ __launch_bounds__(512, 1) void mega_mma_kernel(
    const float* __restrict__ emb_u, const float* __restrict__ emb_r,
    const int* __restrict__ toku, const int* __restrict__ tokr,
    const __nv_bfloat16* __restrict__ WuiT, const __nv_bfloat16* __restrict__ WriT,
    const float* __restrict__ ubih, const float* __restrict__ rbih,
    float* __restrict__ GIu, float* __restrict__ GIr)
{
    extern __shared__ char smem[];
    const int bx = blockIdx.x;
    __nv_bfloat16* A_hi = (__nv_bfloat16*)(smem + MG_HHI);   // [32][HP_]
    __nv_bfloat16* A_lo = (__nv_bfloat16*)(smem + MG_HLO);

    const bool isResp = bx >= 5000;
    const int m0 = isResp ? (bx - 5000)*32 : bx*32;
    const int* toks = isResp ? tokr : toku;
    const float* emb = isResp ? emb_r : emb_u;
    const char* WT = (const char*)(isResp ? WriT : WuiT);
    const float* bih = isResp ? rbih : ubih;
    float* GI = isResp ? GIr : GIu;

    const int tid = threadIdx.x;
    const int wid = tid >> 5, lane = tid & 31;
    const int mh = wid >> 3;
    const int q  = wid & 7;
    const int n0 = q * 96;
    const int g  = lane >> 2, tg = lane & 3;

    const u32 smem_base = (u32)__cvta_generic_to_shared(smem);
    const u32 mb0 = smem_base;
    const u32 mb1 = smem_base + 8;
    const u32 wbuf0 = smem_base + MG_WBUF;

    // gather A rows (fp32 emb -> bf16 hi/lo in smem)
    {
        int row = tid >> 4, c0 = (tid & 15) * 16;
        const float* er = emb + (size_t)__ldg(toks + m0 + row)*256 + c0;
        #pragma unroll
        for (int i = 0; i < 16; i += 4) {
            float4 v = *(const float4*)(er + i);
            float vv[4] = {v.x, v.y, v.z, v.w};
            #pragma unroll
            for (int j = 0; j < 4; j++) {
                __nv_bfloat16 hi = __float2bfloat16(vv[j]);
                A_hi[row*HP_ + c0 + i + j] = hi;
                A_lo[row*HP_ + c0 + i + j] = __float2bfloat16(vv[j] - __bfloat162float(hi));
            }
        }
    }
    if (tid == 0) { mbar_init(mb0, 1); mbar_init(mb1, 1); }
    __syncthreads();
    if (tid == 0) { mbar_expect(mb0, WKTILE_B); cp_bulk(wbuf0, WT, WKTILE_B, mb0); }

    const u32 a_off = (u32)((mh*16 + ((lane>>3)&1)*8 + (lane&7))*HP_*2 + (lane>>4)*16);
    const u32 ahi_base = smem_base + MG_HHI + a_off;
    const u32 alo_base = smem_base + MG_HLO + a_off;
    const int b_pair  = lane >> 4;
    const int b_khalf = ((lane >> 3) & 1) * 16;
    const int b_r     = lane & 7;

    float acc[12][4];
    #pragma unroll
    for (int nt = 0; nt < 12; nt++)
        #pragma unroll
        for (int i = 0; i < 4; i++) acc[nt][i] = 0.f;

    int ph0 = 0, ph1 = 0;
    for (int kt = 0; kt < 16; kt++) {
        const int buf = kt & 1;
        __syncthreads();
        if (tid == 0 && kt < 15) {
            const u32 mbN = (buf ^ 1) ? mb1 : mb0;
            mbar_expect(mbN, WKTILE_B);
            cp_bulk(wbuf0 + (u32)(buf ^ 1)*WKTILE_B, WT + (size_t)(kt + 1)*WKTILE_B, WKTILE_B, mbN);
        }
        if (buf == 0) { mbar_wait(mb0, (u32)ph0); ph0 ^= 1; }
        else          { mbar_wait(mb1, (u32)ph1); ph1 ^= 1; }

        u32 ah[4], al[4];
        ldx4(ah, ahi_base + kt*32);
        ldx4(al, alo_base + kt*32);
        const u32 bhi_base = wbuf0 + (u32)buf*WKTILE_B;
        #pragma unroll
        for (int nt = 0; nt < 12; nt += 2) {
            int gr = n0 + (nt + b_pair)*8 + b_r;
            u32 sw = swz32((u32)(gr*32 + b_khalf));
            u32 bh[4], bl[4];
            ldx4(bh, bhi_base + sw);
            ldx4(bl, bhi_base + 24576 + sw);
            mma_bf16(acc[nt],   ah, bh[0], bh[1]);
            mma_bf16(acc[nt],   al, bh[0], bh[1]);
            mma_bf16(acc[nt],   ah, bl[0], bl[1]);
            mma_bf16(acc[nt+1], ah, bh[2], bh[3]);
            mma_bf16(acc[nt+1], al, bh[2], bh[3]);
            mma_bf16(acc[nt+1], ah, bl[2], bl[3]);
        }
    }

    const int r0 = m0 + mh*16 + g;
    #pragma unroll
    for (int nt = 0; nt < 12; nt++) {
        int c = n0 + nt*8 + tg*2;
        float b0 = __ldg(bih + c), b1 = __ldg(bih + c + 1);
        float2 o0 = make_float2(acc[nt][0] + b0, acc[nt][1] + b1);
        float2 o1 = make_float2(acc[nt][2] + b0, acc[nt][3] + b1);
        *(float2*)(GI + (size_t)r0*768 + c)       = o0;
        *(float2*)(GI + (size_t)(r0 + 8)*768 + c) = o1;
    }
}

// ---------------- persistent mma GRU recurrence (+ MT19937 rider block 104) ----------------
#define CS_P 776
#define OFF_MB    0
#define OFF_HHI   64
#define OFF_HLO   (64 + 16896)
#define OFF_WBUF  (64 + 33792)
#define OFF_CS    (OFF_WBUF + 2*WKTILE_B)
#define SMEM_STEP (OFF_CS + 49664)

__global__ __launch_bounds__(512, 1) void step_persist_kernel(
    const float* __restrict__ GIu, const float* __restrict__ GIr,
    float* __restrict__ hall,
    const __nv_bfloat16* __restrict__ WuT, const __nv_bfloat16* __restrict__ WrT,
    const float* __restrict__ ubhh, const float* __restrict__ rbhh,
    float* __restrict__ respout, float* __restrict__ tables)
{
    extern __shared__ char smem[];
    const int bx = blockIdx.x;
    if (bx == 104) {
        mt_body(tables, (unsigned*)(smem + 64), (unsigned*)(smem + 64 + 2496));
        return;
    }
    __nv_bfloat16* h_hi_s = (__nv_bfloat16*)(smem + OFF_HHI);
    __nv_bfloat16* h_lo_s = (__nv_bfloat16*)(smem + OFF_HLO);
    float*         Cs     = (float*)(smem + OFF_CS);

    const bool isResp = bx >= 100;
    const int row0 = isResp ? NU_ + (bx - 100)*32 : bx*32;
    const char* WT = (const char*)(isResp ? WrT : WuT);
    const float* bhh = isResp ? rbhh : ubhh;
    const float* GI0 = isResp ? (GIr + (size_t)(bx - 100)*32*768)
                              : (GIu + (size_t)bx*32*768);
    const size_t GIstride = isResp ? (size_t)NR_*768 : (size_t)NU_*768;

    const int tid = threadIdx.x;
    const int wid = tid >> 5, lane = tid & 31;
    const int mh = wid >> 3;
    const int q  = wid & 7;
    const int n0 = q * 96;
    const int g  = lane >> 2, tg = lane & 3;
    const int col = tid & 255;

    const u32 smem_base = (u32)__cvta_generic_to_shared(smem);
    const u32 mb0 = smem_base + OFF_MB;
    const u32 mb1 = smem_base + OFF_MB + 8;
    const u32 wbuf0 = smem_base + OFF_WBUF;

    for (int i = tid; i < 32*HP_; i += 512) {
        h_hi_s[i] = __float2bfloat16(0.f);
        h_lo_s[i] = __float2bfloat16(0.f);
    }
    if (tid == 0) { mbar_init(mb0, 1); mbar_init(mb1, 1); }
    __syncthreads();

    if (tid == 0) {
        mbar_expect(mb0, WKTILE_B);
        cp_bulk(wbuf0, WT, WKTILE_B, mb0);
    }

    const float br = __ldg(bhh + col), bz = __ldg(bhh + col + 256), bn = __ldg(bhh + col + 512);

    const u32 a_off = (u32)((mh*16 + ((lane>>3)&1)*8 + (lane&7))*HP_*2 + (lane>>4)*16);
    const u32 ahi_base = smem_base + OFF_HHI + a_off;
    const u32 alo_base = smem_base + OFF_HLO + a_off;
    const int b_pair  = lane >> 4;
    const int b_khalf = ((lane >> 3) & 1) * 16;
    const int b_r     = lane & 7;

    float acc[12][4];
    #pragma unroll
    for (int nt = 0; nt < 12; nt++)
        #pragma unroll
        for (int i = 0; i < 4; i++) acc[nt][i] = 0.f;

    int ph0 = 0, ph1 = 0;
    const int NITER = T_ * 16;
    for (int n = 0; n < NITER; n++) {
        const int t  = n >> 4;
        const int kt = n & 15;
        const int buf = n & 1;

        __syncthreads();
        if (tid == 0 && n + 1 < NITER) {
            const int kt1 = (n + 1) & 15;
            const u32 mbN = (buf ^ 1) ? mb1 : mb0;
            mbar_expect(mbN, WKTILE_B);
            cp_bulk(wbuf0 + (u32)(buf ^ 1)*WKTILE_B, WT + (size_t)kt1*WKTILE_B, WKTILE_B, mbN);
        }
        if (buf == 0) { mbar_wait(mb0, (u32)ph0); ph0 ^= 1; }
        else          { mbar_wait(mb1, (u32)ph1); ph1 ^= 1; }

        u32 ah[4], al[4];
        ldx4(ah, ahi_base + kt*32);
        ldx4(al, alo_base + kt*32);
        const u32 bhi_base = wbuf0 + (u32)buf*WKTILE_B;
        #pragma unroll
        for (int nt = 0; nt < 12; nt += 2) {
            int gr = n0 + (nt + b_pair)*8 + b_r;
            u32 sw = swz32((u32)(gr*32 + b_khalf));
            u32 bh[4], bl[4];
            ldx4(bh, bhi_base + sw);
            ldx4(bl, bhi_base + 24576 + sw);
            mma_bf16(acc[nt],   ah, bh[0], bh[1]);
            mma_bf16(acc[nt],   al, bh[0], bh[1]);
            mma_bf16(acc[nt],   ah, bl[0], bl[1]);
            mma_bf16(acc[nt+1], ah, bh[2], bh[3]);
            mma_bf16(acc[nt+1], al, bh[2], bh[3]);
            mma_bf16(acc[nt+1], ah, bl[2], bl[3]);
        }

        if (kt == 15) {
            const float* GI_t = GI0 + (size_t)t * GIstride;
            #pragma unroll
            for (int w = 0; w < 2; w++) {
                __syncthreads();
                if (mh == w) {
                    #pragma unroll
                    for (int nt = 0; nt < 12; nt++) {
                        int c = n0 + nt*8 + tg*2;
                        Cs[g*CS_P + c]         = acc[nt][0];
                        Cs[g*CS_P + c + 1]     = acc[nt][1];
                        Cs[(g+8)*CS_P + c]     = acc[nt][2];
                        Cs[(g+8)*CS_P + c + 1] = acc[nt][3];
                        acc[nt][0] = 0.f; acc[nt][1] = 0.f; acc[nt][2] = 0.f; acc[nt][3] = 0.f;
                    }
                }
                __syncthreads();
                const int r0w = (tid >> 8) * 8;
                #pragma unroll 4
                for (int r = 0; r < 8; r++) {
                    const int rr = r0w + r;
                    const int rl = w*16 + rr;
                    const int grow = row0 + rl;
                    const float* gi = GI_t + (size_t)rl*768;
                    float aR = Cs[rr*CS_P + col];
                    float aZ = Cs[rr*CS_P + col + 256];
                    float aN = Cs[rr*CS_P + col + 512];
                    float ir = gi[col], iz = gi[col+256], inn = gi[col+512];
                    float rg = 1.f / (1.f + expf(-(ir + aR + br)));
                    float z  = 1.f / (1.f + expf(-(iz + aZ + bz)));
                    float nn = tanhf(inn + rg * (aN + bn));
                    float hold = hall[(size_t)grow*256 + col];
                    float hnew = (1.f - z) * nn + z * hold;
                    hall[(size_t)grow*256 + col] = hnew;
                    __nv_bfloat16 hi = __float2bfloat16(hnew);
                    h_hi_s[rl*HP_ + col] = hi;
                    h_lo_s[rl*HP_ + col] = __float2bfloat16(hnew - __bfloat162float(hi));
                    if (isResp) {
                        int nrow = grow - NU_;
                        respout[(((size_t)(nrow & 1)*T_ + t)*B_ + (nrow >> 1))*256 + col] = hnew;
                    }
                }
            }
        }
    }
}

// ---------------- small GRU body (ctx chain) ----------------
template<int ROWS>
__device__ __forceinline__ void gru_body(
    const float* __restrict__ GI, float* __restrict__ h,
    const float* __restrict__ WT, const float* __restrict__ bhh,
    float* __restrict__ outp, int out_mode, int t, int row0, float* hs)
{
    constexpr int PS = ROWS + 2;
    const int tid = threadIdx.x;
    for (int idx = tid; idx < ROWS*256; idx += 256) {
        int r = idx >> 8, k = idx & 255;
        hs[k*PS + r] = h[(size_t)(row0 + r)*256 + k];
    }
    __syncthreads();
    u64 aR[ROWS/2], aZ[ROWS/2], aN[ROWS/2];
    #pragma unroll
    for (int p = 0; p < ROWS/2; p++) { aR[p]=0ull; aZ[p]=0ull; aN[p]=0ull; }
    const float* Wp = WT + tid;
    #pragma unroll 8
    for (int k = 0; k < 256; k++) {
        float w0 = __ldg(Wp + (size_t)k*768);
        float w1 = __ldg(Wp + (size_t)k*768 + 256);
        float w2 = __ldg(Wp + (size_t)k*768 + 512);
        u64 W0 = pack2(w0, w0), W1 = pack2(w1, w1), W2 = pack2(w2, w2);
        const u64* hp = (const u64*)(hs + k*PS);
        #pragma unroll
        for (int p = 0; p < ROWS/2; p++) {
            u64 hv = hp[p];
            aR[p] = ffma2(hv, W0, aR[p]);
            aZ[p] = ffma2(hv, W1, aZ[p]);
            aN[p] = ffma2(hv, W2, aN[p]);
        }
    }
    const float br = bhh[tid], bz = bhh[tid+256], bn = bhh[tid+512];
    #pragma unroll
    for (int p = 0; p < ROWS/2; p++) {
        float aRl,aRh,aZl,aZh,aNl,aNh;
        unpack2(aR[p], aRl, aRh); unpack2(aZ[p], aZl, aZh); unpack2(aN[p], aNl, aNh);
        #pragma unroll
        for (int q = 0; q < 2; q++) {
            int r = 2*p + q;
            float accR = q ? aRh : aRl;
            float accZ = q ? aZh : aZl;
            float accN = q ? aNh : aNl;
            int grow = row0 + r;
            const float* gi = GI + (size_t)grow*768;
            float ir = gi[tid], iz = gi[tid+256], inn = gi[tid+512];
            float rg = 1.f / (1.f + expf(-(ir + accR + br)));
            float z  = 1.f / (1.f + expf(-(iz + accZ + bz)));
            float nn = tanhf(inn + rg * (accN + bn));
            float hold = hs[tid*PS + r];
            float hnew = (1.f - z) * nn + z * hold;
            h[(size_t)grow*256 + tid] = hnew;
            if (out_mode == 1) outp[(size_t)grow*256 + tid] = hnew;
        }
    }
}

// ---------------- speaker step body ----------------
__device__ void spk_body(const float* __restrict__ ctxout_s,
                         float* __restrict__ hspk, const int* __restrict__ spk,
                         const float* __restrict__ WTi, const float* __restrict__ WTh,
                         const float* __restrict__ bih, const float* __restrict__ bhh,
                         int s, int b0, float* sm)
{
    const int tid = threadIdx.x;
    float* cs  = sm;
    float* hsv = sm + 256*6;
    int id[4];
    #pragma unroll
    for (int r = 0; r < 4; r++) id[r] = spk[(b0 + r)*S_ + s];
    for (int idx = tid; idx < 4*256; idx += 256) {
        int r = idx >> 8, k = idx & 255;
        cs[k*6 + r]  = ctxout_s[(size_t)(b0 + r)*256 + k];
        hsv[k*6 + r] = hspk[((size_t)(b0 + r)*(S_+1) + id[r])*256 + k];
    }
    __syncthreads();
    u64 iR[2]={0ull,0ull}, iZ[2]={0ull,0ull}, iN[2]={0ull,0ull};
    u64 hR[2]={0ull,0ull}, hZ[2]={0ull,0ull}, hN[2]={0ull,0ull};
    #pragma unroll 8
    for (int k = 0; k < 256; k++) {
        float wi0 = __ldg(WTi + (size_t)k*768 + tid);
        float wi1 = __ldg(WTi + (size_t)k*768 + 256 + tid);
        float wi2 = __ldg(WTi + (size_t)k*768 + 512 + tid);
        float wh0 = __ldg(WTh + (size_t)k*768 + tid);
        float wh1 = __ldg(WTh + (size_t)k*768 + 256 + tid);
        float wh2 = __ldg(WTh + (size_t)k*768 + 512 + tid);
        u64 Wi0 = pack2(wi0,wi0), Wi1 = pack2(wi1,wi1), Wi2 = pack2(wi2,wi2);
        u64 Wh0 = pack2(wh0,wh0), Wh1 = pack2(wh1,wh1), Wh2 = pack2(wh2,wh2);
        const u64* cp = (const u64*)(cs + k*6);
        const u64* hp = (const u64*)(hsv + k*6);
        #pragma unroll
        for (int p = 0; p < 2; p++) {
            u64 cv = cp[p], hv = hp[p];
            iR[p] = ffma2(cv, Wi0, iR[p]); iZ[p] = ffma2(cv, Wi1, iZ[p]); iN[p] = ffma2(cv, Wi2, iN[p]);
            hR[p] = ffma2(hv, Wh0, hR[p]); hZ[p] = ffma2(hv, Wh1, hZ[p]); hN[p] = ffma2(hv, Wh2, hN[p]);
        }
    }
    const float bi0 = bih[tid], bi1 = bih[tid+256], bi2 = bih[tid+512];
    const float bh0 = bhh[tid], bh1 = bhh[tid+256], bh2 = bhh[tid+512];
    #pragma unroll
    for (int p = 0; p < 2; p++) {
        float iRl,iRh,iZl,iZh,iNl,iNh,hRl,hRh,hZl,hZh,hNl,hNh;
        unpack2(iR[p],iRl,iRh); unpack2(iZ[p],iZl,iZh); unpack2(iN[p],iNl,iNh);
        unpack2(hR[p],hRl,hRh); unpack2(hZ[p],hZl,hZh); unpack2(hN[p],hNl,hNh);
        #pragma unroll
        for (int q = 0; q < 2; q++) {
            int r = 2*p + q;
            float giR = (q ? iRh : iRl) + bi0;
            float giZ = (q ? iZh : iZl) + bi1;
            float giN = (q ? iNh : iNl) + bi2;
            float ghR = (q ? hRh : hRl) + bh0;
            float ghZ = (q ? hZh : hZl) + bh1;
            float ghN = (q ? hNh : hNl) + bh2;
            float rg = 1.f / (1.f + expf(-(giR + ghR)));
            float z  = 1.f / (1.f + expf(-(giZ + ghZ)));
            float nn = tanhf(giN + rg * ghN);
            float hold = hsv[tid*6 + r];
            float hnew = (1.f - z) * nn + z * hold;
            hspk[((size_t)(b0 + r)*(S_+1) + id[r])*256 + tid] = hnew;
        }
    }
}

__global__ __launch_bounds__(256) void step_cs_kernel(
    const float* __restrict__ GIc, float* __restrict__ hc,
    const float* __restrict__ WTc_h, const float* __restrict__ cbhh,
    float* __restrict__ ctxout, float* __restrict__ hspk, const int* __restrict__ spk,
    const float* __restrict__ WTs_i, const float* __restrict__ WTs_h,
    const float* __restrict__ sbih, const float* __restrict__ sbhh, int i)
{
    __shared__ float sm[256*12];
    if (blockIdx.x < 16) {
        if (i < S_)
            gru_body<4>(GIc + (size_t)i*B_*768, hc, WTc_h, cbhh,
                        ctxout + (size_t)i*B_*256, 1, i, blockIdx.x*4, sm);
    } else {
        int s = i - 1;
        if (s >= 0)
            spk_body(ctxout + (size_t)s*B_*256, hspk, spk, WTs_i, WTs_h, sbih, sbhh,
                     s, (blockIdx.x - 16)*4, sm);
    }
}

// ---------------- prep kernel ----------------
#define SEG_T256 196608
#define SEG_T512 393216
#define PREP_TOTAL (393216 + 196608*7 + 160000 + 6400 + 851968 + 16384 + 835584 + 3264)

__global__ void prep_kernel(
    const int* __restrict__ context, const int* __restrict__ response, const int* __restrict__ spk,
    const float* __restrict__ uWih, const float* __restrict__ uWhh,
    const float* __restrict__ cWih, const float* __restrict__ cWhh,
    const float* __restrict__ rWih, const float* __restrict__ rWhh,
    const float* __restrict__ sWih, const float* __restrict__ sWhh,
    float* __restrict__ WTc_i, float* __restrict__ WTc_h,
    float* __restrict__ WTs_i, float* __restrict__ WTs_h,
    __nv_bfloat16* __restrict__ WuiT, __nv_bfloat16* __restrict__ WriT,
    __nv_bfloat16* __restrict__ WuT,  __nv_bfloat16* __restrict__ WrT,
    int* __restrict__ toku, int* __restrict__ tokr,
    float* __restrict__ hall,
    float* __restrict__ hc, float* __restrict__ hspk, int* __restrict__ pres)
{
    long i = (long)blockIdx.x*256 + threadIdx.x;
    if (i >= PREP_TOTAL) return;
    if (i < SEG_T512) { int g = (int)(i / 512), k = (int)(i % 512); WTc_i[k*768 + g] = cWih[i]; return; }
    i -= SEG_T512;
    if (i < SEG_T256) { int g = i >> 8, k = i & 255; WTc_h[k*768 + g] = cWhh[i]; return; }
    i -= SEG_T256;
    if (i < SEG_T256) { int g = i >> 8, k = i & 255; WTs_i[k*768 + g] = sWih[i]; return; }
    i -= SEG_T256;
    if (i < SEG_T256) { int g = i >> 8, k = i & 255; WTs_h[k*768 + g] = sWhh[i]; return; }
    i -= SEG_T256;
    if (i < SEG_T256) {
        int gr = (int)(i >> 8), k = (int)(i & 255);
        float w = uWih[i];
        __nv_bfloat16 hi = __float2bfloat16(w);
        __nv_bfloat16 lo = __float2bfloat16(w - __bfloat162float(hi));
        int kt = k >> 4, kk = k & 15;
        u32 raw = (u32)(gr*32 + ((kk >> 3) << 4));
        u32 byte_in = (raw ^ ((raw >> 3) & 0x70)) + ((kk & 7) << 1);
        int e = (int)(byte_in >> 1);
        WuiT[kt*24576 + e] = hi;
        WuiT[kt*24576 + 12288 + e] = lo;
        return;
    }
    i -= SEG_T256;
    if (i < SEG_T256) {
        int gr = (int)(i >> 8), k = (int)(i & 255);
        float w = rWih[i];
        __nv_bfloat16 hi = __float2bfloat16(w);
        __nv_bfloat16 lo = __float2bfloat16(w - __bfloat162float(hi));
        int kt = k >> 4, kk = k & 15;
        u32 raw = (u32)(gr*32 + ((kk >> 3) << 4));
        u32 byte_in = (raw ^ ((raw >> 3) & 0x70)) + ((kk & 7) << 1);
        int e = (int)(byte_in >> 1);
        WriT[kt*24576 + e] = hi;
        WriT[kt*24576 + 12288 + e] = lo;
        return;
    }
    i -= SEG_T256;
    if (i < SEG_T256) {
        int gr = (int)(i >> 8), k = (int)(i & 255);
        float w = uWhh[i];
        __nv_bfloat16 hi = __float2bfloat16(w);
        __nv_bfloat16 lo = __float2bfloat16(w - __bfloat162float(hi));
        int kt = k >> 4, kk = k & 15;
        u32 raw = (u32)(gr*32 + ((kk >> 3) << 4));
        u32 byte_in = (raw ^ ((raw >> 3) & 0x70)) + ((kk & 7) << 1);
        int e = (int)(byte_in >> 1);
        WuT[kt*24576 + e] = hi;
        WuT[kt*24576 + 12288 + e] = lo;
        return;
    }
    i -= SEG_T256;
    if (i < SEG_T256) {
        int gr = (int)(i >> 8), k = (int)(i & 255);
        float w = rWhh[i];
        __nv_bfloat16 hi = __float2bfloat16(w);
        __nv_bfloat16 lo = __float2bfloat16(w - __bfloat162float(hi));
        int kt = k >> 4, kk = k & 15;
        u32 raw = (u32)(gr*32 + ((kk >> 3) << 4));
        u32 byte_in = (raw ^ ((raw >> 3) & 0x70)) + ((kk & 7) << 1);
        int e = (int)(byte_in >> 1);
        WrT[kt*24576 + e] = hi;
        WrT[kt*24576 + 12288 + e] = lo;
        return;
    }
    i -= SEG_T256;
    if (i < MU_) { int t = (int)(i / NU_), n = (int)(i % NU_); toku[i] = context[n*T_ + t]; return; }
    i -= MU_;
    if (i < MR_) { int t = (int)(i / NR_), n = (int)(i % NR_); tokr[i] = response[n*T_ + t]; return; }
    i -= MR_;
    if (i < NALL_*H_) { hall[i] = 0.f; return; }
    i -= NALL_*H_;
    if (i < B_*H_) { hc[i] = 0.f; return; }
    i -= B_*H_;
    if (i < B_*(S_+1)*H_) { hspk[i] = 0.f; return; }
    i -= B_*(S_+1)*H_;
    {
        int b = (int)(i / (S_+1)), a = (int)(i % (S_+1));
        int p = 0;
        for (int s = 0; s < S_; s++) p |= (spk[b*S_ + s] == a);
        pres[i] = p;
    }
}

// ---------------- ctx input gather ----------------
__global__ void ctx_in_kernel(const float* __restrict__ hall, const float* __restrict__ tab,
                              const int* __restrict__ spk, float* __restrict__ cin) {
    int i = blockIdx.x * blockDim.x + threadIdx.x;
    if (i < MC_ * 2 * H_) {
        int row = i / (2*H_), j = i % (2*H_);
        int s = row / B_, b = row % B_;
        float v;
        if (j < H_) v = hall[((size_t)b*S_ + s)*H_ + j];
        else        v = tab[((size_t)b*(S_+1) + spk[b*S_ + s])*H_ + (j - H_)];
        cin[i] = v;
    }
}

// ---------------- epilogue ----------------
#define EPI_TOTAL (16384 + 32768 + 835584)
__global__ void epilogue_kernel(float* __restrict__ out, const float* __restrict__ hall,
                                const float* __restrict__ hspk, const int* __restrict__ pres)
{
    long i = (long)blockIdx.x*256 + threadIdx.x;
    if (i >= EPI_TOTAL) return;
    if (i < 16384) { out[OFF_CTXHID + i] = out[OFF_CTXOUT + (size_t)(S_-1)*B_*H_ + i]; return; }
    i -= 16384;
    if (i < 32768) {
        int n = (int)(i >> 8), c = (int)(i & 255);
        int r = n % R_, b = n / R_;
        out[OFF_RESPHID + ((size_t)r*B_ + b)*H_ + c] = hall[(size_t)(NU_ + n)*H_ + c];
        return;
    }
    i -= 32768;
    {
        int ba = (int)(i >> 8);
        int p = pres[ba];
        out[OFF_SPKEMB + i] = p ? hspk[i] : 0.f;
        if ((i & 255) == 0) {
            int a = ba % (S_+1);
            out[OFF_MASK + ba] = (p && a > 0) ? 1.f : 0.f;
        }
    }
}

// ---------------- launch ----------------
extern "C" void kernel_launch(void* const* d_in, const int* in_sizes, int n_in,
                              void* d_out, int out_size)
{
    const int*   context  = (const int*)d_in[0];
    const int*   response = (const int*)d_in[1];
    const int*   spk      = (const int*)d_in[2];
    const float* emb_u    = (const float*)d_in[3];
    const float* emb_r    = (const float*)d_in[4];
    const float* uWih = (const float*)d_in[5];
    const float* uWhh = (const float*)d_in[6];
    const float* ubih = (const float*)d_in[7];
    const float* ubhh = (const float*)d_in[8];
    const float* cWih = (const float*)d_in[9];
    const float* cWhh = (const float*)d_in[10];
    const float* cbih = (const float*)d_in[11];
    const float* cbhh = (const float*)d_in[12];
    const float* rWih = (const float*)d_in[13];
    const float* rWhh = (const float*)d_in[14];
    const float* rbih = (const float*)d_in[15];
    const float* rbhh = (const float*)d_in[16];
    const float* sWih = (const float*)d_in[17];
    const float* sWhh = (const float*)d_in[18];
    const float* sbih = (const float*)d_in[19];
    const float* sbhh = (const float*)d_in[20];
    float* out = (float*)d_out;

    void *p;
    float *tab, *GIu, *GIc, *GIr, *hall, *hc, *hspk, *cin;
    float *WTc_i, *WTc_h, *WTs_i, *WTs_h;
    __nv_bfloat16 *WuT, *WrT, *WuiT, *WriT;
    int *toku, *tokr, *pres;
    cudaGetSymbolAddress(&p, g_tables); tab  = (float*)p;
    cudaGetSymbolAddress(&p, g_GIu);    GIu  = (float*)p;
    cudaGetSymbolAddress(&p, g_GIc);    GIc  = (float*)p;
    cudaGetSymbolAddress(&p, g_GIr);    GIr  = (float*)p;
    cudaGetSymbolAddress(&p, g_hall);   hall = (float*)p;
    cudaGetSymbolAddress(&p, g_hc);     hc   = (float*)p;
    cudaGetSymbolAddress(&p, g_hspk);   hspk = (float*)p;
    cudaGetSymbolAddress(&p, g_ctxin);  cin  = (float*)p;
    cudaGetSymbolAddress(&p, g_WTc_i);  WTc_i = (float*)p;
    cudaGetSymbolAddress(&p, g_WTc_h);  WTc_h = (float*)p;
    cudaGetSymbolAddress(&p, g_WTs_i);  WTs_i = (float*)p;
    cudaGetSymbolAddress(&p, g_WTs_h);  WTs_h = (float*)p;
    cudaGetSymbolAddress(&p, g_WuT);    WuT  = (__nv_bfloat16*)p;
    cudaGetSymbolAddress(&p, g_WrT);    WrT  = (__nv_bfloat16*)p;
    cudaGetSymbolAddress(&p, g_WuiT);   WuiT = (__nv_bfloat16*)p;
    cudaGetSymbolAddress(&p, g_WriT);   WriT = (__nv_bfloat16*)p;
    cudaGetSymbolAddress(&p, g_toku);   toku = (int*)p;
    cudaGetSymbolAddress(&p, g_tokr);   tokr = (int*)p;
    cudaGetSymbolAddress(&p, g_present); pres = (int*)p;

    cudaFuncSetAttribute(step_persist_kernel, cudaFuncAttributeMaxDynamicSharedMemorySize, SMEM_STEP);
    cudaFuncSetAttribute(mega_mma_kernel, cudaFuncAttributeMaxDynamicSharedMemorySize, SMEM_MEGA);

    // 1. prep
    prep_kernel<<<(PREP_TOTAL + 255)/256, 256>>>(
        context, response, spk,
        uWih, uWhh, cWih, cWhh, rWih, rWhh, sWih, sWhh,
        WTc_i, WTc_h, WTs_i, WTs_h,
        WuiT, WriT, WuT, WrT,
        toku, tokr, hall, hc, hspk, pres);

    // 2. tensorized input GEMMs
    mega_mma_kernel<<<5200, 512, SMEM_MEGA>>>(emb_u, emb_r, toku, tokr,
                                              WuiT, WriT, ubih, rbih, GIu, GIr);

    // 3. recurrence (104 blocks) + MT19937 rider (block 104)
    step_persist_kernel<<<105, 512, SMEM_STEP>>>(GIu, GIr, hall,
                                                 WuT, WrT,
                                                 ubhh, rbhh, out + OFF_RESPOUT, tab);

    // 4. context input + GEMM (fp32)
    ctx_in_kernel<<<(MC_*2*H_ + 255)/256, 256>>>(hall, tab, spk, cin);
    gemm_ctx_kernel<<<150, 256>>>(cin, WTc_i, cbih, GIc);

    // 5. pipelined ctx + speaker chains (launch chain; unroll-8 bodies)
    for (int i = 0; i <= S_; i++)
        step_cs_kernel<<<32, 256>>>(GIc, hc, WTc_h, cbhh, out + OFF_CTXOUT,
                                    hspk, spk, WTs_i, WTs_h, sbih, sbhh, i);

    // 6. epilogue
    epilogue_kernel<<<(EPI_TOTAL + 255)/256, 256>>>(out, hall, hspk, pres);
}

// round 17
// speedup vs baseline: 1.1742x; 1.1742x over previous
#include <cuda_runtime.h>
#include <cuda_bf16.h>
#include <math.h>

typedef unsigned long long u64;
typedef unsigned int u32;

// ---------------- constants ----------------
#define B_  64
#define S_  50
#define T_  50
#define R_  2
#define H_  256
#define NU_ (B_*S_)          // 3200
#define NR_ (B_*R_)          // 128
#define NALL_ (NU_+NR_)      // 3328
#define MU_ (T_*NU_)         // 160000
#define MR_ (T_*NR_)         // 6400
#define MC_ (S_*B_)          // 3200
#define TAB_N (B_*(S_+1)*H_) // 835584

// output offsets (f32 elements)
#define OFF_CTXOUT   0
#define OFF_CTXHID   819200
#define OFF_RESPOUT  835584
#define OFF_RESPHID  2473984
#define OFF_SPKEMB   2506752
#define OFF_MASK     3342336

// ---------------- static device scratch ----------------
__device__ float g_tables[TAB_N];
__device__ float g_GIu[(size_t)MU_*768];
__device__ float g_GIc[(size_t)MC_*768];
__device__ float g_GIs[(size_t)MC_*768];
__device__ float g_GIr[(size_t)MR_*768];
__device__ float g_hall[NALL_*H_];
__device__ float g_hc[B_*H_];
__device__ float g_hspk[B_*(S_+1)*H_];
__device__ float g_ctxin[MC_*2*H_];
__device__ float g_WTc_i[2*H_*768], g_WTc_h[H_*768];
__device__ float g_WTs_i[H_*768],  g_WTs_h[H_*768];
__device__ __nv_bfloat16 g_WuT[16*24576],  g_WrT[16*24576];    // Whh (recurrence)
__device__ __nv_bfloat16 g_WuiT[16*24576], g_WriT[16*24576];   // Wih (input GEMM)
__device__ int   g_toku[MU_];
__device__ int   g_tokr[MR_];
__device__ int   g_present[B_*(S_+1)];

// ---------------- helpers ----------------
__device__ __forceinline__ u64 pack2(float lo, float hi) {
    u64 r; asm("mov.b64 %0, {%1,%2};" : "=l"(r) : "f"(lo), "f"(hi)); return r;
}
__device__ __forceinline__ void unpack2(u64 a, float& lo, float& hi) {
    asm("mov.b64 {%0,%1}, %2;" : "=f"(lo), "=f"(hi) : "l"(a));
}
__device__ __forceinline__ u64 ffma2(u64 a, u64 b, u64 c) {
    u64 d; asm("fma.rn.f32x2 %0, %1, %2, %3;" : "=l"(d) : "l"(a), "l"(b), "l"(c)); return d;
}
__device__ __forceinline__ void ldx4(u32* r, u32 addr) {
    asm volatile("ldmatrix.sync.aligned.m8n8.x4.shared.b16 {%0,%1,%2,%3}, [%4];"
        : "=r"(r[0]), "=r"(r[1]), "=r"(r[2]), "=r"(r[3]) : "r"(addr));
}
__device__ __forceinline__ void mma_bf16(float* c, const u32* a, u32 b0, u32 b1) {
    asm volatile(
        "mma.sync.aligned.m16n8k16.row.col.f32.bf16.bf16.f32 "
        "{%0,%1,%2,%3}, {%4,%5,%6,%7}, {%8,%9}, {%0,%1,%2,%3};"
        : "+f"(c[0]), "+f"(c[1]), "+f"(c[2]), "+f"(c[3])
        : "r"(a[0]), "r"(a[1]), "r"(a[2]), "r"(a[3]), "r"(b0), "r"(b1));
}
__device__ __forceinline__ void mbar_init(u32 a, u32 c) {
    asm volatile("mbarrier.init.shared.b64 [%0], %1;" :: "r"(a), "r"(c) : "memory");
}
__device__ __forceinline__ void mbar_expect(u32 a, u32 bytes) {
    asm volatile("mbarrier.arrive.expect_tx.shared.b64 _, [%0], %1;" :: "r"(a), "r"(bytes) : "memory");
}
__device__ __forceinline__ void mbar_wait(u32 a, u32 parity) {
    u32 done;
    asm volatile(
        "{\n\t.reg .pred p;\n\t"
        "mbarrier.try_wait.parity.acquire.cta.shared::cta.b64 p, [%1], %2;\n\t"
        "selp.b32 %0, 1, 0, p;\n\t}"
        : "=r"(done) : "r"(a), "r"(parity) : "memory");
    if (!done) {
        asm volatile(
            "{\n\t.reg .pred P1;\n\t"
            "WL_%=:\n\t"
            "mbarrier.try_wait.parity.acquire.cta.shared::cta.b64 P1, [%0], %1, 0x989680;\n\t"
            "@P1 bra.uni WD_%=;\n\t"
            "bra.uni WL_%=;\n\t"
            "WD_%=:\n\t}"
            :: "r"(a), "r"(parity) : "memory");
    }
}
__device__ __forceinline__ void cp_bulk(u32 dst_smem, const void* src, u32 bytes, u32 mbar) {
    asm volatile("cp.async.bulk.shared::cta.global.mbarrier::complete_tx::bytes [%0], [%1], %2, [%3];"
        :: "r"(dst_smem), "l"(src), "r"(bytes), "r"(mbar) : "memory");
}
__device__ __forceinline__ u32 swz32(u32 x) { return x ^ ((x >> 3) & 0x70); }

// ---------------- MT19937 (NumPy-exact state; fp32 output conversion) ----------------
__device__ __forceinline__ unsigned mt_twist_fn(unsigned u, unsigned v) {
    unsigned y = (u & 0x80000000u) | (v & 0x7fffffffu);
    return (y >> 1) ^ ((v & 1u) ? 0x9908b0dfu : 0u);
}
__device__ __forceinline__ unsigned mt_temper(unsigned y) {
    y ^= y >> 11; y ^= (y << 7) & 0x9d2c5680u; y ^= (y << 15) & 0xefc60000u; y ^= y >> 18;
    return y;
}
__device__ void mt_body(float* __restrict__ tables, unsigned* bufA, unsigned* bufB) {
    const int tid = threadIdx.x;
    const int nthr = blockDim.x;
    if (tid == 0) {
        unsigned s = 1u; bufA[0] = s;
        for (int i = 1; i < 624; i++) { s = 1812433253u * (s ^ (s >> 30)) + (unsigned)i; bufA[i] = s; }
    }
    __syncthreads();
    unsigned* cur = bufA; unsigned* nxt = bufB;
    const int NTW = (2*TAB_N + 623) / 624;
    for (int tw = 0; tw < NTW; tw++) {
        if (tid < 227) nxt[tid] = cur[tid + 397] ^ mt_twist_fn(cur[tid], cur[tid + 1]);
        __syncthreads();
        if (tid < 227) { int i = 227 + tid; nxt[i] = nxt[i - 227] ^ mt_twist_fn(cur[i], cur[i + 1]); }
        __syncthreads();
        if (tid < 170) {
            int i = 454 + tid;
            unsigned v = (i == 623) ? nxt[0] : cur[i + 1];
            nxt[i] = nxt[i - 227] ^ mt_twist_fn(cur[i], v);
        }
        __syncthreads();
        for (int o = tid; o < 312; o += nthr) {
            int outIdx = tw * 312 + o;
            if (outIdx < TAB_N) {
                unsigned a  = mt_temper(nxt[2*o])   >> 5;
                unsigned bv = mt_temper(nxt[2*o+1]) >> 6;
                tables[outIdx] = fmaf((float)a, 67108864.0f, (float)bv) * (1.0f/9007199254740992.0f);
            }
        }
        unsigned* t2 = cur; cur = nxt; nxt = t2;
    }
}

// ---------------- fp32 GEMM body (ctx path only) ----------------
__device__ __forceinline__ void gemm_body(
    const float* __restrict__ A,
    const float* __restrict__ BT, const float* __restrict__ bias, float* __restrict__ C,
    int m0, int n0, int K, float* As, float* Bs)
{
    const int tid  = threadIdx.x;
    const int arow = tid >> 2;
    const int akc  = (tid & 3) << 2;
    const int bk   = tid >> 4;
    const int bc   = (tid & 15) << 3;
    const int tr   = tid >> 4;
    const int tc   = tid & 15;

    const float* arp0 = A + (size_t)(m0 + arow) * K;
    const float* arp1 = A + (size_t)(m0 + arow + 64) * K;
    float4 ra0 = *(const float4*)(arp0 + akc);
    float4 ra1 = *(const float4*)(arp1 + akc);
    float4 rb0 = *(const float4*)(BT + (size_t)bk * 768 + n0 + bc);
    float4 rb1 = *(const float4*)(BT + (size_t)bk * 768 + n0 + bc + 4);
    {
        As[(akc+0)*128 + arow] = ra0.x; As[(akc+1)*128 + arow] = ra0.y;
        As[(akc+2)*128 + arow] = ra0.z; As[(akc+3)*128 + arow] = ra0.w;
        As[(akc+0)*128 + arow+64] = ra1.x; As[(akc+1)*128 + arow+64] = ra1.y;
        As[(akc+2)*128 + arow+64] = ra1.z; As[(akc+3)*128 + arow+64] = ra1.w;
        *(float4*)(Bs + bk*128 + bc)     = rb0;
        *(float4*)(Bs + bk*128 + bc + 4) = rb1;
    }
    __syncthreads();

    u64 acc[8][4];
    #pragma unroll
    for (int i = 0; i < 8; i++)
        #pragma unroll
        for (int j = 0; j < 4; j++) acc[i][j] = 0ull;

    int buf = 0;
    for (int k0 = 16; k0 <= K; k0 += 16) {
        const bool more = (k0 < K);
        if (more) {
            ra0 = *(const float4*)(arp0 + k0 + akc);
            ra1 = *(const float4*)(arp1 + k0 + akc);
            rb0 = *(const float4*)(BT + (size_t)(k0 + bk) * 768 + n0 + bc);
            rb1 = *(const float4*)(BT + (size_t)(k0 + bk) * 768 + n0 + bc + 4);
        }
        const float* Asb = As + buf * 2048;
        const float* Bsb = Bs + buf * 2048;
        #pragma unroll
        for (int kk = 0; kk < 16; kk++) {
            float4 av0 = *(const float4*)(Asb + kk*128 + tr*8);
            float4 av1 = *(const float4*)(Asb + kk*128 + tr*8 + 4);
            u64 bb0 = *(const u64*)(Bsb + kk*128 + tc*4);
            u64 bb1 = *(const u64*)(Bsb + kk*128 + tc*4 + 2);
            u64 bb2 = *(const u64*)(Bsb + kk*128 + 64 + tc*4);
            u64 bb3 = *(const u64*)(Bsb + kk*128 + 64 + tc*4 + 2);
            float av[8] = {av0.x, av0.y, av0.z, av0.w, av1.x, av1.y, av1.z, av1.w};
            #pragma unroll
            for (int i = 0; i < 8; i++) {
                u64 aa = pack2(av[i], av[i]);
                acc[i][0] = ffma2(aa, bb0, acc[i][0]);
                acc[i][1] = ffma2(aa, bb1, acc[i][1]);
                acc[i][2] = ffma2(aa, bb2, acc[i][2]);
                acc[i][3] = ffma2(aa, bb3, acc[i][3]);
            }
        }
        if (more) {
            float* Asb1 = As + (buf ^ 1) * 2048;
            float* Bsb1 = Bs + (buf ^ 1) * 2048;
            Asb1[(akc+0)*128 + arow] = ra0.x; Asb1[(akc+1)*128 + arow] = ra0.y;
            Asb1[(akc+2)*128 + arow] = ra0.z; Asb1[(akc+3)*128 + arow] = ra0.w;
            Asb1[(akc+0)*128 + arow+64] = ra1.x; Asb1[(akc+1)*128 + arow+64] = ra1.y;
            Asb1[(akc+2)*128 + arow+64] = ra1.z; Asb1[(akc+3)*128 + arow+64] = ra1.w;
            *(float4*)(Bsb1 + bk*128 + bc)     = rb0;
            *(float4*)(Bsb1 + bk*128 + bc + 4) = rb1;
        }
        __syncthreads();
        buf ^= 1;
    }

    float4 bba = *(const float4*)(bias + n0 + tc*4);
    float4 bbb = *(const float4*)(bias + n0 + 64 + tc*4);
    #pragma unroll
    for (int i = 0; i < 8; i++) {
        int gm = m0 + tr*8 + i;
        float x0,x1,x2,x3,y0,y1,y2,y3;
        unpack2(acc[i][0], x0, x1); unpack2(acc[i][1], x2, x3);
        unpack2(acc[i][2], y0, y1); unpack2(acc[i][3], y2, y3);
        float4 o0 = make_float4(x0+bba.x, x1+bba.y, x2+bba.z, x3+bba.w);
        float4 o1 = make_float4(y0+bbb.x, y1+bbb.y, y2+bbb.z, y3+bbb.w);
        *(float4*)(C + (size_t)gm*768 + n0 + tc*4)      = o0;
        *(float4*)(C + (size_t)gm*768 + n0 + 64 + tc*4) = o1;
    }
}

__global__ __launch_bounds__(256) void gemm_ctx_kernel(
    const float* __restrict__ cin, const float* __restrict__ WTc_i,
    const float* __restrict__ cbih, float* __restrict__ GIc)
{
    __shared__ float As[2*16*128];
    __shared__ float Bs[2*16*128];
    int mb = blockIdx.x % 25, nb = blockIdx.x / 25;
    gemm_body(cin, WTc_i, cbih, GIc, mb*128, nb*128, 512, As, Bs);
}

// ---------------- tensorized input GEMM ----------------
#define HP_ 264
#define WKTILE_B 49152
#define MG_HHI   64
#define MG_HLO   (64 + 16896)
#define MG_WBUF  (64 + 33792)
#define SMEM_MEGA (MG_WBUF + 2*WKTILE_B)   // 132160

__global__ __launch_bounds__(512, 1) void mega_mma_kernel(
    const float* __restrict__ emb_u, const float* __restrict__ emb_r,
    const int* __restrict__ toku, const int* __restrict__ tokr,
    const __nv_bfloat16* __restrict__ WuiT, const __nv_bfloat16* __restrict__ WriT,
    const float* __restrict__ ubih, const float* __restrict__ rbih,
    float* __restrict__ GIu, float* __restrict__ GIr)
{
    extern __shared__ char smem[];
    const int bx = blockIdx.x;
    __nv_bfloat16* A_hi = (__nv_bfloat16*)(smem + MG_HHI);   // [32][HP_]
    __nv_bfloat16* A_lo = (__nv_bfloat16*)(smem + MG_HLO);

    const bool isResp = bx >= 5000;
    const int m0 = isResp ? (bx - 5000)*32 : bx*32;
    const int* toks = isResp ? tokr : toku;
    const float* emb = isResp ? emb_r : emb_u;
    const char* WT = (const char*)(isResp ? WriT : WuiT);
    const float* bih = isResp ? rbih : ubih;
    float* GI = isResp ? GIr : GIu;

    const int tid = threadIdx.x;
    const int wid = tid >> 5, lane = tid & 31;
    const int mh = wid >> 3;
    const int q  = wid & 7;
    const int n0 = q * 96;
    const int g  = lane >> 2, tg = lane & 3;

    const u32 smem_base = (u32)__cvta_generic_to_shared(smem);
    const u32 mb0 = smem_base;
    const u32 mb1 = smem_base + 8;
    const u32 wbuf0 = smem_base + MG_WBUF;

    // gather A rows (fp32 emb -> bf16 hi/lo in smem)
    {
        int row = tid >> 4, c0 = (tid & 15) * 16;
        const float* er = emb + (size_t)__ldg(toks + m0 + row)*256 + c0;
        #pragma unroll
        for (int i = 0; i < 16; i += 4) {
            float4 v = *(const float4*)(er + i);
            float vv[4] = {v.x, v.y, v.z, v.w};
            #pragma unroll
            for (int j = 0; j < 4; j++) {
                __nv_bfloat16 hi = __float2bfloat16(vv[j]);
                A_hi[row*HP_ + c0 + i + j] = hi;
                A_lo[row*HP_ + c0 + i + j] = __float2bfloat16(vv[j] - __bfloat162float(hi));
            }
        }
    }
    if (tid == 0) { mbar_init(mb0, 1); mbar_init(mb1, 1); }
    __syncthreads();
    if (tid == 0) { mbar_expect(mb0, WKTILE_B); cp_bulk(wbuf0, WT, WKTILE_B, mb0); }

    const u32 a_off = (u32)((mh*16 + ((lane>>3)&1)*8 + (lane&7))*HP_*2 + (lane>>4)*16);
    const u32 ahi_base = smem_base + MG_HHI + a_off;
    const u32 alo_base = smem_base + MG_HLO + a_off;
    const int b_pair  = lane >> 4;
    const int b_khalf = ((lane >> 3) & 1) * 16;
    const int b_r     = lane & 7;

    float acc[12][4];
    #pragma unroll
    for (int nt = 0; nt < 12; nt++)
        #pragma unroll
        for (int i = 0; i < 4; i++) acc[nt][i] = 0.f;

    int ph0 = 0, ph1 = 0;
    for (int kt = 0; kt < 16; kt++) {
        const int buf = kt & 1;
        __syncthreads();
        if (tid == 0 && kt < 15) {
            const u32 mbN = (buf ^ 1) ? mb1 : mb0;
            mbar_expect(mbN, WKTILE_B);
            cp_bulk(wbuf0 + (u32)(buf ^ 1)*WKTILE_B, WT + (size_t)(kt + 1)*WKTILE_B, WKTILE_B, mbN);
        }
        if (buf == 0) { mbar_wait(mb0, (u32)ph0); ph0 ^= 1; }
        else          { mbar_wait(mb1, (u32)ph1); ph1 ^= 1; }

        u32 ah[4], al[4];
        ldx4(ah, ahi_base + kt*32);
        ldx4(al, alo_base + kt*32);
        const u32 bhi_base = wbuf0 + (u32)buf*WKTILE_B;
        #pragma unroll
        for (int nt = 0; nt < 12; nt += 2) {
            int gr = n0 + (nt + b_pair)*8 + b_r;
            u32 sw = swz32((u32)(gr*32 + b_khalf));
            u32 bh[4], bl[4];
            ldx4(bh, bhi_base + sw);
            ldx4(bl, bhi_base + 24576 + sw);
            mma_bf16(acc[nt],   ah, bh[0], bh[1]);
            mma_bf16(acc[nt],   al, bh[0], bh[1]);
            mma_bf16(acc[nt],   ah, bl[0], bl[1]);
            mma_bf16(acc[nt+1], ah, bh[2], bh[3]);
            mma_bf16(acc[nt+1], al, bh[2], bh[3]);
            mma_bf16(acc[nt+1], ah, bl[2], bl[3]);
        }
    }

    const int r0 = m0 + mh*16 + g;
    #pragma unroll
    for (int nt = 0; nt < 12; nt++) {
        int c = n0 + nt*8 + tg*2;
        float b0 = __ldg(bih + c), b1 = __ldg(bih + c + 1);
        float2 o0 = make_float2(acc[nt][0] + b0, acc[nt][1] + b1);
        float2 o1 = make_float2(acc[nt][2] + b0, acc[nt][3] + b1);
        *(float2*)(GI + (size_t)r0*768 + c)       = o0;
        *(float2*)(GI + (size_t)(r0 + 8)*768 + c) = o1;
    }
}

// ---------------- persistent mma GRU recurrence (+ MT19937 rider block 104) ----------------
#define CS_P 776
#define OFF_MB    0
#define OFF_HHI   64
#define OFF_HLO   (64 + 16896)
#define OFF_WBUF  (64 + 33792)
#define OFF_CS    (OFF_WBUF + 2*WKTILE_B)
#define SMEM_STEP (OFF_CS + 49664)

__global__ __launch_bounds__(512, 1) void step_persist_kernel(
    const float* __restrict__ GIu, const float* __restrict__ GIr,
    float* __restrict__ hall,
    const __nv_bfloat16* __restrict__ WuT, const __nv_bfloat16* __restrict__ WrT,
    const float* __restrict__ ubhh, const float* __restrict__ rbhh,
    float* __restrict__ respout, float* __restrict__ tables)
{
    extern __shared__ char smem[];
    const int bx = blockIdx.x;
    if (bx == 104) {
        mt_body(tables, (unsigned*)(smem + 64), (unsigned*)(smem + 64 + 2496));
        return;
    }
    __nv_bfloat16* h_hi_s = (__nv_bfloat16*)(smem + OFF_HHI);
    __nv_bfloat16* h_lo_s = (__nv_bfloat16*)(smem + OFF_HLO);
    float*         Cs     = (float*)(smem + OFF_CS);

    const bool isResp = bx >= 100;
    const int row0 = isResp ? NU_ + (bx - 100)*32 : bx*32;
    const char* WT = (const char*)(isResp ? WrT : WuT);
    const float* bhh = isResp ? rbhh : ubhh;
    const float* GI0 = isResp ? (GIr + (size_t)(bx - 100)*32*768)
                              : (GIu + (size_t)bx*32*768);
    const size_t GIstride = isResp ? (size_t)NR_*768 : (size_t)NU_*768;

    const int tid = threadIdx.x;
    const int wid = tid >> 5, lane = tid & 31;
    const int mh = wid >> 3;
    const int q  = wid & 7;
    const int n0 = q * 96;
    const int g  = lane >> 2, tg = lane & 3;
    const int col = tid & 255;

    const u32 smem_base = (u32)__cvta_generic_to_shared(smem);
    const u32 mb0 = smem_base + OFF_MB;
    const u32 mb1 = smem_base + OFF_MB + 8;
    const u32 wbuf0 = smem_base + OFF_WBUF;

    for (int i = tid; i < 32*HP_; i += 512) {
        h_hi_s[i] = __float2bfloat16(0.f);
        h_lo_s[i] = __float2bfloat16(0.f);
    }
    if (tid == 0) { mbar_init(mb0, 1); mbar_init(mb1, 1); }
    __syncthreads();

    if (tid == 0) {
        mbar_expect(mb0, WKTILE_B);
        cp_bulk(wbuf0, WT, WKTILE_B, mb0);
    }

    const float br = __ldg(bhh + col), bz = __ldg(bhh + col + 256), bn = __ldg(bhh + col + 512);

    const u32 a_off = (u32)((mh*16 + ((lane>>3)&1)*8 + (lane&7))*HP_*2 + (lane>>4)*16);
    const u32 ahi_base = smem_base + OFF_HHI + a_off;
    const u32 alo_base = smem_base + OFF_HLO + a_off;
    const int b_pair  = lane >> 4;
    const int b_khalf = ((lane >> 3) & 1) * 16;
    const int b_r     = lane & 7;

    float acc[12][4];
    #pragma unroll
    for (int nt = 0; nt < 12; nt++)
        #pragma unroll
        for (int i = 0; i < 4; i++) acc[nt][i] = 0.f;

    int ph0 = 0, ph1 = 0;
    const int NITER = T_ * 16;
    for (int n = 0; n < NITER; n++) {
        const int t  = n >> 4;
        const int kt = n & 15;
        const int buf = n & 1;

        __syncthreads();
        if (tid == 0 && n + 1 < NITER) {
            const int kt1 = (n + 1) & 15;
            const u32 mbN = (buf ^ 1) ? mb1 : mb0;
            mbar_expect(mbN, WKTILE_B);
            cp_bulk(wbuf0 + (u32)(buf ^ 1)*WKTILE_B, WT + (size_t)kt1*WKTILE_B, WKTILE_B, mbN);
        }
        if (buf == 0) { mbar_wait(mb0, (u32)ph0); ph0 ^= 1; }
        else          { mbar_wait(mb1, (u32)ph1); ph1 ^= 1; }

        u32 ah[4], al[4];
        ldx4(ah, ahi_base + kt*32);
        ldx4(al, alo_base + kt*32);
        const u32 bhi_base = wbuf0 + (u32)buf*WKTILE_B;
        #pragma unroll
        for (int nt = 0; nt < 12; nt += 2) {
            int gr = n0 + (nt + b_pair)*8 + b_r;
            u32 sw = swz32((u32)(gr*32 + b_khalf));
            u32 bh[4], bl[4];
            ldx4(bh, bhi_base + sw);
            ldx4(bl, bhi_base + 24576 + sw);
            mma_bf16(acc[nt],   ah, bh[0], bh[1]);
            mma_bf16(acc[nt],   al, bh[0], bh[1]);
            mma_bf16(acc[nt],   ah, bl[0], bl[1]);
            mma_bf16(acc[nt+1], ah, bh[2], bh[3]);
            mma_bf16(acc[nt+1], al, bh[2], bh[3]);
            mma_bf16(acc[nt+1], ah, bl[2], bl[3]);
        }

        if (kt == 15) {
            const float* GI_t = GI0 + (size_t)t * GIstride;
            #pragma unroll
            for (int w = 0; w < 2; w++) {
                __syncthreads();
                if (mh == w) {
                    #pragma unroll
                    for (int nt = 0; nt < 12; nt++) {
                        int c = n0 + nt*8 + tg*2;
                        Cs[g*CS_P + c]         = acc[nt][0];
                        Cs[g*CS_P + c + 1]     = acc[nt][1];
                        Cs[(g+8)*CS_P + c]     = acc[nt][2];
                        Cs[(g+8)*CS_P + c + 1] = acc[nt][3];
                        acc[nt][0] = 0.f; acc[nt][1] = 0.f; acc[nt][2] = 0.f; acc[nt][3] = 0.f;
                    }
                }
                __syncthreads();
                const int r0w = (tid >> 8) * 8;
                #pragma unroll 4
                for (int r = 0; r < 8; r++) {
                    const int rr = r0w + r;
                    const int rl = w*16 + rr;
                    const int grow = row0 + rl;
                    const float* gi = GI_t + (size_t)rl*768;
                    float aR = Cs[rr*CS_P + col];
                    float aZ = Cs[rr*CS_P + col + 256];
                    float aN = Cs[rr*CS_P + col + 512];
                    float ir = gi[col], iz = gi[col+256], inn = gi[col+512];
                    float rg = 1.f / (1.f + expf(-(ir + aR + br)));
                    float z  = 1.f / (1.f + expf(-(iz + aZ + bz)));
                    float nn = tanhf(inn + rg * (aN + bn));
                    float hold = hall[(size_t)grow*256 + col];
                    float hnew = (1.f - z) * nn + z * hold;
                    hall[(size_t)grow*256 + col] = hnew;
                    __nv_bfloat16 hi = __float2bfloat16(hnew);
                    h_hi_s[rl*HP_ + col] = hi;
                    h_lo_s[rl*HP_ + col] = __float2bfloat16(hnew - __bfloat162float(hi));
                    if (isResp) {
                        int nrow = grow - NU_;
                        respout[(((size_t)(nrow & 1)*T_ + t)*B_ + (nrow >> 1))*256 + col] = hnew;
                    }
                }
            }
        }
    }
}

// ---------------- small GRU body (ctx chain) ----------------
template<int ROWS>
__device__ __forceinline__ void gru_body(
    const float* __restrict__ GI, float* __restrict__ h,
    const float* __restrict__ WT, const float* __restrict__ bhh,
    float* __restrict__ outp, int out_mode, int t, int row0, float* hs)
{
    constexpr int PS = ROWS + 2;
    const int tid = threadIdx.x;
    for (int idx = tid; idx < ROWS*256; idx += 256) {
        int r = idx >> 8, k = idx & 255;
        hs[k*PS + r] = h[(size_t)(row0 + r)*256 + k];
    }
    __syncthreads();
    u64 aR[ROWS/2], aZ[ROWS/2], aN[ROWS/2];
    #pragma unroll
    for (int p = 0; p < ROWS/2; p++) { aR[p]=0ull; aZ[p]=0ull; aN[p]=0ull; }
    const float* Wp = WT + tid;
    #pragma unroll 8
    for (int k = 0; k < 256; k++) {
        float w0 = __ldg(Wp + (size_t)k*768);
        float w1 = __ldg(Wp + (size_t)k*768 + 256);
        float w2 = __ldg(Wp + (size_t)k*768 + 512);
        u64 W0 = pack2(w0, w0), W1 = pack2(w1, w1), W2 = pack2(w2, w2);
        const u64* hp = (const u64*)(hs + k*PS);
        #pragma unroll
        for (int p = 0; p < ROWS/2; p++) {
            u64 hv = hp[p];
            aR[p] = ffma2(hv, W0, aR[p]);
            aZ[p] = ffma2(hv, W1, aZ[p]);
            aN[p] = ffma2(hv, W2, aN[p]);
        }
    }
    const float br = bhh[tid], bz = bhh[tid+256], bn = bhh[tid+512];
    #pragma unroll
    for (int p = 0; p < ROWS/2; p++) {
        float aRl,aRh,aZl,aZh,aNl,aNh;
        unpack2(aR[p], aRl, aRh); unpack2(aZ[p], aZl, aZh); unpack2(aN[p], aNl, aNh);
        #pragma unroll
        for (int q = 0; q < 2; q++) {
            int r = 2*p + q;
            float accR = q ? aRh : aRl;
            float accZ = q ? aZh : aZl;
            float accN = q ? aNh : aNl;
            int grow = row0 + r;
            const float* gi = GI + (size_t)grow*768;
            float ir = gi[tid], iz = gi[tid+256], inn = gi[tid+512];
            float rg = 1.f / (1.f + expf(-(ir + accR + br)));
            float z  = 1.f / (1.f + expf(-(iz + accZ + bz)));
            float nn = tanhf(inn + rg * (accN + bn));
            float hold = hs[tid*PS + r];
            float hnew = (1.f - z) * nn + z * hold;
            h[(size_t)grow*256 + tid] = hnew;
            if (out_mode == 1) outp[(size_t)grow*256 + tid] = hnew;
        }
    }
}

// ---------------- speaker input-gate stage: GIs[s] = ctxout[s]·WsiT + bi ----------------
__device__ void gis_body(const float* __restrict__ ctxout_s, float* __restrict__ GIs_s,
                         const float* __restrict__ WTi, const float* __restrict__ bih,
                         int b0, float* hs)
{
    const int tid = threadIdx.x;
    for (int idx = tid; idx < 4*256; idx += 256) {
        int r = idx >> 8, k = idx & 255;
        hs[k*6 + r] = ctxout_s[(size_t)(b0 + r)*256 + k];
    }
    __syncthreads();
    u64 aR[2] = {0ull, 0ull}, aZ[2] = {0ull, 0ull}, aN[2] = {0ull, 0ull};
    const float* Wp = WTi + tid;
    #pragma unroll 8
    for (int k = 0; k < 256; k++) {
        float w0 = __ldg(Wp + (size_t)k*768);
        float w1 = __ldg(Wp + (size_t)k*768 + 256);
        float w2 = __ldg(Wp + (size_t)k*768 + 512);
        u64 W0 = pack2(w0, w0), W1 = pack2(w1, w1), W2 = pack2(w2, w2);
        const u64* hp = (const u64*)(hs + k*6);
        #pragma unroll
        for (int p = 0; p < 2; p++) {
            u64 hv = hp[p];
            aR[p] = ffma2(hv, W0, aR[p]);
            aZ[p] = ffma2(hv, W1, aZ[p]);
            aN[p] = ffma2(hv, W2, aN[p]);
        }
    }
    const float bi0 = bih[tid], bi1 = bih[tid+256], bi2 = bih[tid+512];
    #pragma unroll
    for (int p = 0; p < 2; p++) {
        float aRl,aRh,aZl,aZh,aNl,aNh;
        unpack2(aR[p], aRl, aRh); unpack2(aZ[p], aZl, aZh); unpack2(aN[p], aNl, aNh);
        #pragma unroll
        for (int q = 0; q < 2; q++) {
            int r = 2*p + q;
            float* gis = GIs_s + (size_t)(b0 + r)*768;
            gis[tid]       = (q ? aRh : aRl) + bi0;
            gis[tid + 256] = (q ? aZh : aZl) + bi1;
            gis[tid + 512] = (q ? aNh : aNl) + bi2;
        }
    }
}

// ---------------- speaker hidden stage: gates from GIs, Wh only ----------------
__device__ void spkh_body(const float* __restrict__ GIs_s,
                          float* __restrict__ hspk, const int* __restrict__ spk,
                          const float* __restrict__ WTh, const float* __restrict__ bhh,
                          int s, int b0, float* hsv)
{
    const int tid = threadIdx.x;
    int id[4];
    #pragma unroll
    for (int r = 0; r < 4; r++) id[r] = spk[(b0 + r)*S_ + s];
    for (int idx = tid; idx < 4*256; idx += 256) {
        int r = idx >> 8, k = idx & 255;
        hsv[k*6 + r] = hspk[((size_t)(b0 + r)*(S_+1) + id[r])*256 + k];
    }
    __syncthreads();
    u64 hR[2] = {0ull, 0ull}, hZ[2] = {0ull, 0ull}, hN[2] = {0ull, 0ull};
    const float* Wp = WTh + tid;
    #pragma unroll 8
    for (int k = 0; k < 256; k++) {
        float w0 = __ldg(Wp + (size_t)k*768);
        float w1 = __ldg(Wp + (size_t)k*768 + 256);
        float w2 = __ldg(Wp + (size_t)k*768 + 512);
        u64 W0 = pack2(w0, w0), W1 = pack2(w1, w1), W2 = pack2(w2, w2);
        const u64* hp = (const u64*)(hsv + k*6);
        #pragma unroll
        for (int p = 0; p < 2; p++) {
            u64 hv = hp[p];
            hR[p] = ffma2(hv, W0, hR[p]);
            hZ[p] = ffma2(hv, W1, hZ[p]);
            hN[p] = ffma2(hv, W2, hN[p]);
        }
    }
    const float bh0 = bhh[tid], bh1 = bhh[tid+256], bh2 = bhh[tid+512];
    #pragma unroll
    for (int p = 0; p < 2; p++) {
        float hRl,hRh,hZl,hZh,hNl,hNh;
        unpack2(hR[p], hRl, hRh); unpack2(hZ[p], hZl, hZh); unpack2(hN[p], hNl, hNh);
        #pragma unroll
        for (int q = 0; q < 2; q++) {
            int r = 2*p + q;
            const float* gis = GIs_s + (size_t)(b0 + r)*768;
            float giR = gis[tid];
            float giZ = gis[tid + 256];
            float giN = gis[tid + 512];
            float ghR = (q ? hRh : hRl) + bh0;
            float ghZ = (q ? hZh : hZl) + bh1;
            float ghN = (q ? hNh : hNl) + bh2;
            float rg = 1.f / (1.f + expf(-(giR + ghR)));
            float z  = 1.f / (1.f + expf(-(giZ + ghZ)));
            float nn = tanhf(giN + rg * ghN);
            float hold = hsv[tid*6 + r];
            float hnew = (1.f - z) * nn + z * hold;
            hspk[((size_t)(b0 + r)*(S_+1) + id[r])*256 + tid] = hnew;
        }
    }
}

// 3-stage pipelined chain: ctx step i | GIs step i-1 | spk-hidden step i-2
__global__ __launch_bounds__(256) void step_cs_kernel(
    const float* __restrict__ GIc, float* __restrict__ hc,
    const float* __restrict__ WTc_h, const float* __restrict__ cbhh,
    float* __restrict__ ctxout,
    float* __restrict__ GIs, float* __restrict__ hspk, const int* __restrict__ spk,
    const float* __restrict__ WTs_i, const float* __restrict__ WTs_h,
    const float* __restrict__ sbih, const float* __restrict__ sbhh, int i)
{
    __shared__ float sm[256*6];
    const int bx = blockIdx.x;
    if (bx < 16) {
        if (i < S_)
            gru_body<4>(GIc + (size_t)i*B_*768, hc, WTc_h, cbhh,
                        ctxout + (size_t)i*B_*256, 1, i, bx*4, sm);
    } else if (bx < 32) {
        int s = i - 1;
        if (s >= 0 && s < S_)
            gis_body(ctxout + (size_t)s*B_*256, GIs + (size_t)s*B_*768,
                     WTs_i, sbih, (bx - 16)*4, sm);
    } else {
        int s = i - 2;
        if (s >= 0 && s < S_)
            spkh_body(GIs + (size_t)s*B_*768, hspk, spk, WTs_h, sbhh,
                      s, (bx - 32)*4, sm);
    }
}

// ---------------- prep kernel ----------------
#define SEG_T256 196608
#define SEG_T512 393216
#define PREP_TOTAL (393216 + 196608*7 + 160000 + 6400 + 851968 + 16384 + 835584 + 3264)

__global__ void prep_kernel(
    const int* __restrict__ context, const int* __restrict__ response, const int* __restrict__ spk,
    const float* __restrict__ uWih, const float* __restrict__ uWhh,
    const float* __restrict__ cWih, const float* __restrict__ cWhh,
    const float* __restrict__ rWih, const float* __restrict__ rWhh,
    const float* __restrict__ sWih, const float* __restrict__ sWhh,
    float* __restrict__ WTc_i, float* __restrict__ WTc_h,
    float* __restrict__ WTs_i, float* __restrict__ WTs_h,
    __nv_bfloat16* __restrict__ WuiT, __nv_bfloat16* __restrict__ WriT,
    __nv_bfloat16* __restrict__ WuT,  __nv_bfloat16* __restrict__ WrT,
    int* __restrict__ toku, int* __restrict__ tokr,
    float* __restrict__ hall,
    float* __restrict__ hc, float* __restrict__ hspk, int* __restrict__ pres)
{
    long i = (long)blockIdx.x*256 + threadIdx.x;
    if (i >= PREP_TOTAL) return;
    if (i < SEG_T512) { int g = (int)(i / 512), k = (int)(i % 512); WTc_i[k*768 + g] = cWih[i]; return; }
    i -= SEG_T512;
    if (i < SEG_T256) { int g = i >> 8, k = i & 255; WTc_h[k*768 + g] = cWhh[i]; return; }
    i -= SEG_T256;
    if (i < SEG_T256) { int g = i >> 8, k = i & 255; WTs_i[k*768 + g] = sWih[i]; return; }
    i -= SEG_T256;
    if (i < SEG_T256) { int g = i >> 8, k = i & 255; WTs_h[k*768 + g] = sWhh[i]; return; }
    i -= SEG_T256;
    if (i < SEG_T256) {
        int gr = (int)(i >> 8), k = (int)(i & 255);
        float w = uWih[i];
        __nv_bfloat16 hi = __float2bfloat16(w);
        __nv_bfloat16 lo = __float2bfloat16(w - __bfloat162float(hi));
        int kt = k >> 4, kk = k & 15;
        u32 raw = (u32)(gr*32 + ((kk >> 3) << 4));
        u32 byte_in = (raw ^ ((raw >> 3) & 0x70)) + ((kk & 7) << 1);
        int e = (int)(byte_in >> 1);
        WuiT[kt*24576 + e] = hi;
        WuiT[kt*24576 + 12288 + e] = lo;
        return;
    }
    i -= SEG_T256;
    if (i < SEG_T256) {
        int gr = (int)(i >> 8), k = (int)(i & 255);
        float w = rWih[i];
        __nv_bfloat16 hi = __float2bfloat16(w);
        __nv_bfloat16 lo = __float2bfloat16(w - __bfloat162float(hi));
        int kt = k >> 4, kk = k & 15;
        u32 raw = (u32)(gr*32 + ((kk >> 3) << 4));
        u32 byte_in = (raw ^ ((raw >> 3) & 0x70)) + ((kk & 7) << 1);
        int e = (int)(byte_in >> 1);
        WriT[kt*24576 + e] = hi;
        WriT[kt*24576 + 12288 + e] = lo;
        return;
    }
    i -= SEG_T256;
    if (i < SEG_T256) {
        int gr = (int)(i >> 8), k = (int)(i & 255);
        float w = uWhh[i];
        __nv_bfloat16 hi = __float2bfloat16(w);
        __nv_bfloat16 lo = __float2bfloat16(w - __bfloat162float(hi));
        int kt = k >> 4, kk = k & 15;
        u32 raw = (u32)(gr*32 + ((kk >> 3) << 4));
        u32 byte_in = (raw ^ ((raw >> 3) & 0x70)) + ((kk & 7) << 1);
        int e = (int)(byte_in >> 1);
        WuT[kt*24576 + e] = hi;
        WuT[kt*24576 + 12288 + e] = lo;
        return;
    }
    i -= SEG_T256;
    if (i < SEG_T256) {
        int gr = (int)(i >> 8), k = (int)(i & 255);
        float w = rWhh[i];
        __nv_bfloat16 hi = __float2bfloat16(w);
        __nv_bfloat16 lo = __float2bfloat16(w - __bfloat162float(hi));
        int kt = k >> 4, kk = k & 15;
        u32 raw = (u32)(gr*32 + ((kk >> 3) << 4));
        u32 byte_in = (raw ^ ((raw >> 3) & 0x70)) + ((kk & 7) << 1);
        int e = (int)(byte_in >> 1);
        WrT[kt*24576 + e] = hi;
        WrT[kt*24576 + 12288 + e] = lo;
        return;
    }
    i -= SEG_T256;
    if (i < MU_) { int t = (int)(i / NU_), n = (int)(i % NU_); toku[i] = context[n*T_ + t]; return; }
    i -= MU_;
    if (i < MR_) { int t = (int)(i / NR_), n = (int)(i % NR_); tokr[i] = response[n*T_ + t]; return; }
    i -= MR_;
    if (i < NALL_*H_) { hall[i] = 0.f; return; }
    i -= NALL_*H_;
    if (i < B_*H_) { hc[i] = 0.f; return; }
    i -= B_*H_;
    if (i < B_*(S_+1)*H_) { hspk[i] = 0.f; return; }
    i -= B_*(S_+1)*H_;
    {
        int b = (int)(i / (S_+1)), a = (int)(i % (S_+1));
        int p = 0;
        for (int s = 0; s < S_; s++) p |= (spk[b*S_ + s] == a);
        pres[i] = p;
    }
}

// ---------------- ctx input gather ----------------
__global__ void ctx_in_kernel(const float* __restrict__ hall, const float* __restrict__ tab,
                              const int* __restrict__ spk, float* __restrict__ cin) {
    int i = blockIdx.x * blockDim.x + threadIdx.x;
    if (i < MC_ * 2 * H_) {
        int row = i / (2*H_), j = i % (2*H_);
        int s = row / B_, b = row % B_;
        float v;
        if (j < H_) v = hall[((size_t)b*S_ + s)*H_ + j];
        else        v = tab[((size_t)b*(S_+1) + spk[b*S_ + s])*H_ + (j - H_)];
        cin[i] = v;
    }
}

// ---------------- epilogue ----------------
#define EPI_TOTAL (16384 + 32768 + 835584)
__global__ void epilogue_kernel(float* __restrict__ out, const float* __restrict__ hall,
                                const float* __restrict__ hspk, const int* __restrict__ pres)
{
    long i = (long)blockIdx.x*256 + threadIdx.x;
    if (i >= EPI_TOTAL) return;
    if (i < 16384) { out[OFF_CTXHID + i] = out[OFF_CTXOUT + (size_t)(S_-1)*B_*H_ + i]; return; }
    i -= 16384;
    if (i < 32768) {
        int n = (int)(i >> 8), c = (int)(i & 255);
        int r = n % R_, b = n / R_;
        out[OFF_RESPHID + ((size_t)r*B_ + b)*H_ + c] = hall[(size_t)(NU_ + n)*H_ + c];
        return;
    }
    i -= 32768;
    {
        int ba = (int)(i >> 8);
        int p = pres[ba];
        out[OFF_SPKEMB + i] = p ? hspk[i] : 0.f;
        if ((i & 255) == 0) {
            int a = ba % (S_+1);
            out[OFF_MASK + ba] = (p && a > 0) ? 1.f : 0.f;
        }
    }
}

// ---------------- launch ----------------
extern "C" void kernel_launch(void* const* d_in, const int* in_sizes, int n_in,
                              void* d_out, int out_size)
{
    const int*   context  = (const int*)d_in[0];
    const int*   response = (const int*)d_in[1];
    const int*   spk      = (const int*)d_in[2];
    const float* emb_u    = (const float*)d_in[3];
    const float* emb_r    = (const float*)d_in[4];
    const float* uWih = (const float*)d_in[5];
    const float* uWhh = (const float*)d_in[6];
    const float* ubih = (const float*)d_in[7];
    const float* ubhh = (const float*)d_in[8];
    const float* cWih = (const float*)d_in[9];
    const float* cWhh = (const float*)d_in[10];
    const float* cbih = (const float*)d_in[11];
    const float* cbhh = (const float*)d_in[12];
    const float* rWih = (const float*)d_in[13];
    const float* rWhh = (const float*)d_in[14];
    const float* rbih = (const float*)d_in[15];
    const float* rbhh = (const float*)d_in[16];
    const float* sWih = (const float*)d_in[17];
    const float* sWhh = (const float*)d_in[18];
    const float* sbih = (const float*)d_in[19];
    const float* sbhh = (const float*)d_in[20];
    float* out = (float*)d_out;

    void *p;
    float *tab, *GIu, *GIc, *GIsb, *GIr, *hall, *hc, *hspk, *cin;
    float *WTc_i, *WTc_h, *WTs_i, *WTs_h;
    __nv_bfloat16 *WuT, *WrT, *WuiT, *WriT;
    int *toku, *tokr, *pres;
    cudaGetSymbolAddress(&p, g_tables); tab  = (float*)p;
    cudaGetSymbolAddress(&p, g_GIu);    GIu  = (float*)p;
    cudaGetSymbolAddress(&p, g_GIc);    GIc  = (float*)p;
    cudaGetSymbolAddress(&p, g_GIs);    GIsb = (float*)p;
    cudaGetSymbolAddress(&p, g_GIr);    GIr  = (float*)p;
    cudaGetSymbolAddress(&p, g_hall);   hall = (float*)p;
    cudaGetSymbolAddress(&p, g_hc);     hc   = (float*)p;
    cudaGetSymbolAddress(&p, g_hspk);   hspk = (float*)p;
    cudaGetSymbolAddress(&p, g_ctxin);  cin  = (float*)p;
    cudaGetSymbolAddress(&p, g_WTc_i);  WTc_i = (float*)p;
    cudaGetSymbolAddress(&p, g_WTc_h);  WTc_h = (float*)p;
    cudaGetSymbolAddress(&p, g_WTs_i);  WTs_i = (float*)p;
    cudaGetSymbolAddress(&p, g_WTs_h);  WTs_h = (float*)p;
    cudaGetSymbolAddress(&p, g_WuT);    WuT  = (__nv_bfloat16*)p;
    cudaGetSymbolAddress(&p, g_WrT);    WrT  = (__nv_bfloat16*)p;
    cudaGetSymbolAddress(&p, g_WuiT);   WuiT = (__nv_bfloat16*)p;
    cudaGetSymbolAddress(&p, g_WriT);   WriT = (__nv_bfloat16*)p;
    cudaGetSymbolAddress(&p, g_toku);   toku = (int*)p;
    cudaGetSymbolAddress(&p, g_tokr);   tokr = (int*)p;
    cudaGetSymbolAddress(&p, g_present); pres = (int*)p;

    cudaFuncSetAttribute(step_persist_kernel, cudaFuncAttributeMaxDynamicSharedMemorySize, SMEM_STEP);
    cudaFuncSetAttribute(mega_mma_kernel, cudaFuncAttributeMaxDynamicSharedMemorySize, SMEM_MEGA);

    // 1. prep
    prep_kernel<<<(PREP_TOTAL + 255)/256, 256>>>(
        context, response, spk,
        uWih, uWhh, cWih, cWhh, rWih, rWhh, sWih, sWhh,
        WTc_i, WTc_h, WTs_i, WTs_h,
        WuiT, WriT, WuT, WrT,
        toku, tokr, hall, hc, hspk, pres);

    // 2. tensorized input GEMMs
    mega_mma_kernel<<<5200, 512, SMEM_MEGA>>>(emb_u, emb_r, toku, tokr,
                                              WuiT, WriT, ubih, rbih, GIu, GIr);

    // 3. recurrence (104 blocks) + MT19937 rider (block 104)
    step_persist_kernel<<<105, 512, SMEM_STEP>>>(GIu, GIr, hall,
                                                 WuT, WrT,
                                                 ubhh, rbhh, out + OFF_RESPOUT, tab);

    // 4. context input + GEMM (fp32)
    ctx_in_kernel<<<(MC_*2*H_ + 255)/256, 256>>>(hall, tab, spk, cin);
    gemm_ctx_kernel<<<150, 256>>>(cin, WTc_i, cbih, GIc);

    // 5. 3-stage pipelined ctx + GIs + spk-hidden chain (52 launches, 48 blocks)
    for (int i = 0; i <= S_ + 1; i++)
        step_cs_kernel<<<48, 256>>>(GIc, hc, WTc_h, cbhh, out + OFF_CTXOUT,
                                    GIsb, hspk, spk, WTs_i, WTs_h, sbih, sbhh, i);

    // 6. epilogue
    epilogue_kernel<<<(EPI_TOTAL + 255)/256, 256>>>(out, hall, hspk, pres);
}